// round 1
// baseline (speedup 1.0000x reference)
#include <cuda_runtime.h>

// Problem constants (fixed shapes from reference):
// x: (N=8, M=32, C=128, H=32, W=32) fp32.  D = 1024.
// 4096 independent Gram-Schmidt problems (one per (m,c)), each over
// 8 vectors of length 1024. Output has identical layout to input.
#define NV 8              // number of vectors per problem (N)
#define DLEN 1024         // vector length (H*W)
#define NPROB 4096        // M*C
#define NSTRIDE_F4 (NPROB * DLEN / 4)   // stride between n-slices in float4 units = 1048576

__device__ __forceinline__ float dot4(float4 a, float4 b) {
    return a.x * b.x + a.y * b.y + a.z * b.z + a.w * b.w;
}

// Reduce k partial sums (k <= 8) across the 256-thread block.
// On return every thread holds the full block sums in vals[0..k).
__device__ __forceinline__ void block_reduce(float* vals, int k,
                                             float (*smem)[8], int lane, int warp) {
    for (int j = 0; j < k; j++) {
        float s = vals[j];
        s += __shfl_xor_sync(0xffffffffu, s, 16);
        s += __shfl_xor_sync(0xffffffffu, s, 8);
        s += __shfl_xor_sync(0xffffffffu, s, 4);
        s += __shfl_xor_sync(0xffffffffu, s, 2);
        s += __shfl_xor_sync(0xffffffffu, s, 1);
        if (lane == 0) smem[j][warp] = s;
    }
    __syncthreads();
    for (int j = 0; j < k; j++) {
        float s = 0.0f;
        #pragma unroll
        for (int w = 0; w < 8; w++) s += smem[j][w];
        vals[j] = s;
    }
    __syncthreads();  // smem reused next round
}

__global__ void __launch_bounds__(256, 4)
gram_schmidt_kernel(const float* __restrict__ x, float* __restrict__ out) {
    const int p    = blockIdx.x;        // m*128 + c
    const int tid  = threadIdx.x;       // 0..255; owns elements d = 4*tid .. 4*tid+3
    const int lane = tid & 31;
    const int warp = tid >> 5;

    const float4* __restrict__ xin =
        reinterpret_cast<const float4*>(x) + (size_t)p * (DLEN / 4) + tid;
    float4* __restrict__ xout =
        reinterpret_cast<float4*>(out) + (size_t)p * (DLEN / 4) + tid;

    __shared__ float smem[8][8];

    // Load all 8 vectors for this problem into registers (coalesced float4).
    float4 v[NV];
    #pragma unroll
    for (int n = 0; n < NV; n++) {
        v[n] = xin[(size_t)n * NSTRIDE_F4];
    }

    // ---- normalize v0 ----
    {
        float nrm[1];
        nrm[0] = dot4(v[0], v[0]);
        block_reduce(nrm, 1, smem, lane, warp);
        float inv = (nrm[0] > 0.0f) ? (1.0f / sqrtf(nrm[0])) : 0.0f;
        v[0].x *= inv; v[0].y *= inv; v[0].z *= inv; v[0].w *= inv;
    }

    // ---- classical Gram-Schmidt for v1..v7 ----
    #pragma unroll
    for (int i = 1; i < NV; i++) {
        float c[NV];
        for (int j = 0; j < i; j++) c[j] = dot4(v[i], v[j]);
        block_reduce(c, i, smem, lane, warp);

        // subtract projection onto all previous bases (one-shot, like reference)
        for (int j = 0; j < i; j++) {
            v[i].x -= c[j] * v[j].x;
            v[i].y -= c[j] * v[j].y;
            v[i].z -= c[j] * v[j].z;
            v[i].w -= c[j] * v[j].w;
        }

        float nrm[1];
        nrm[0] = dot4(v[i], v[i]);
        block_reduce(nrm, 1, smem, lane, warp);
        float inv = (nrm[0] > 0.0f) ? (1.0f / sqrtf(nrm[0])) : 0.0f;
        v[i].x *= inv; v[i].y *= inv; v[i].z *= inv; v[i].w *= inv;
    }

    // Store (same layout as input).
    #pragma unroll
    for (int n = 0; n < NV; n++) {
        xout[(size_t)n * NSTRIDE_F4] = v[n];
    }
}

extern "C" void kernel_launch(void* const* d_in, const int* in_sizes, int n_in,
                              void* d_out, int out_size) {
    const float* x = (const float*)d_in[0];
    float* out = (float*)d_out;
    gram_schmidt_kernel<<<NPROB, 256>>>(x, out);
}

// round 3
// speedup vs baseline: 1.0482x; 1.0482x over previous
#include <cuda_runtime.h>

// x: (N=8, M=32, C=128, H=32, W=32) fp32.  D = H*W = 1024.
// 4096 independent classical Gram-Schmidt problems (one per (m,c)),
// each over NV=8 vectors of length 1024.
//
// Strategy: one block (256 threads) per problem, 4 elements (1 float4) per
// thread per vector.  Compute the full 8x8 Gram matrix in ONE block
// reduction, then derive all GS coefficients + inverse norms from the Gram
// matrix with a tiny replicated triangular recursion, and apply the
// orthogonalization entirely in registers.  2 barriers per block total.
#define NV 8
#define DLEN 1024
#define NPROB 4096
#define NSTRIDE_F4 (NPROB * DLEN / 4)   // 1048576 float4 between n-slices
#define NG 36                           // lower-triangular Gram entries

__device__ __forceinline__ float dot4(float4 a, float4 b) {
    return a.x * b.x + a.y * b.y + a.z * b.z + a.w * b.w;
}

__global__ void __launch_bounds__(256, 2)
gram_schmidt_kernel(const float* __restrict__ x, float* __restrict__ out) {
    const int p    = blockIdx.x;
    const int tid  = threadIdx.x;
    const int lane = tid & 31;
    const int warp = tid >> 5;

    const float4* __restrict__ xin =
        reinterpret_cast<const float4*>(x) + (size_t)p * (DLEN / 4) + tid;
    float4* __restrict__ xout =
        reinterpret_cast<float4*>(out) + (size_t)p * (DLEN / 4) + tid;

    __shared__ float red[8][NG];   // per-warp partial Gram
    __shared__ float Gf[NG];       // final Gram (packed lower triangle)

    // ---- load all 8 vectors (coalesced float4, fully batched for MLP) ----
    float4 v[NV];
    #pragma unroll
    for (int n = 0; n < NV; n++) v[n] = xin[(size_t)n * NSTRIDE_F4];

    // ---- per-thread partial Gram matrix (packed lower triangle) ----
    float g[NG];
    #pragma unroll
    for (int i = 0; i < NV; i++) {
        #pragma unroll
        for (int j = 0; j <= i; j++) {
            g[i * (i + 1) / 2 + j] = dot4(v[i], v[j]);
        }
    }

    // ---- single block reduction of all 36 values ----
    #pragma unroll
    for (int t = 0; t < NG; t++) {
        float s = g[t];
        s += __shfl_xor_sync(0xffffffffu, s, 16);
        s += __shfl_xor_sync(0xffffffffu, s, 8);
        s += __shfl_xor_sync(0xffffffffu, s, 4);
        s += __shfl_xor_sync(0xffffffffu, s, 2);
        s += __shfl_xor_sync(0xffffffffu, s, 1);
        if (lane == 0) red[warp][t] = s;
    }
    __syncthreads();
    if (tid < NG) {
        float s = 0.0f;
        #pragma unroll
        for (int w = 0; w < 8; w++) s += red[w][tid];
        Gf[tid] = s;
    }
    __syncthreads();

    // ---- triangular recursion: classical GS coefficients from Gram ----
    // b_j = sum_k T[j][k] v_k.  c_{i,j} = v_i . b_j = sum_k T[j][k] G[i][k].
    // ||w_i||^2 = G_ii - sum_j c_{i,j}^2.
    // Replicated in every thread (register resident, ~250 flops).
    float T[NG];
    {
        float g00 = Gf[0];
        float inv = (g00 > 0.0f) ? rsqrtf(g00) : 0.0f;
        T[0] = inv;
        v[0].x *= inv; v[0].y *= inv; v[0].z *= inv; v[0].w *= inv;
    }

    #pragma unroll
    for (int i = 1; i < NV; i++) {
        float c[NV];
        #pragma unroll
        for (int j = 0; j < i; j++) {
            float s = 0.0f;
            #pragma unroll
            for (int k = 0; k <= j; k++) {
                s += T[j * (j + 1) / 2 + k] * Gf[i * (i + 1) / 2 + k];
            }
            c[j] = s;
        }

        float n2 = Gf[i * (i + 1) / 2 + i];
        #pragma unroll
        for (int j = 0; j < i; j++) n2 -= c[j] * c[j];
        float inv = (n2 > 0.0f) ? rsqrtf(n2) : 0.0f;

        // apply to this thread's slice: v_i <- inv * (v_i - sum_j c_j b_j)
        #pragma unroll
        for (int j = 0; j < i; j++) {
            v[i].x -= c[j] * v[j].x;
            v[i].y -= c[j] * v[j].y;
            v[i].z -= c[j] * v[j].z;
            v[i].w -= c[j] * v[j].w;
        }
        v[i].x *= inv; v[i].y *= inv; v[i].z *= inv; v[i].w *= inv;

        // extend T with row i (needed for later coefficients)
        #pragma unroll
        for (int k = 0; k < i; k++) {
            float s = 0.0f;
            #pragma unroll
            for (int j = k; j < i; j++) {
                s -= c[j] * T[j * (j + 1) / 2 + k];
            }
            T[i * (i + 1) / 2 + k] = s * inv;
        }
        T[i * (i + 1) / 2 + i] = inv;
    }

    // ---- store ----
    #pragma unroll
    for (int n = 0; n < NV; n++) xout[(size_t)n * NSTRIDE_F4] = v[n];
}

extern "C" void kernel_launch(void* const* d_in, const int* in_sizes, int n_in,
                              void* d_out, int out_size) {
    const float* x = (const float*)d_in[0];
    float* out = (float*)d_out;
    gram_schmidt_kernel<<<NPROB, 256>>>(x, out);
}

// round 4
// speedup vs baseline: 1.5190x; 1.4491x over previous
#include <cuda_runtime.h>

// x: (N=8, M=32, C=128, H=32, W=32) fp32.  D = H*W = 1024.
// 4096 independent classical Gram-Schmidt problems (one per (m,c)),
// each over NV=8 vectors of length 1024.
//
// Pipeline per block (256 threads, 1 float4/thread/vector):
//  A) load 8 float4, compute 36 packed-Gram partials, STS to part[t][tid]
//  B) 8 warps cooperatively reduce the 36 entries (LDS.128 + 5-shuffle)
//  C) warp 0 runs the tiny triangular recursion Gram -> T (GS transform
//     matrix, inverse norms folded into the diagonal), broadcasts via smem
//  D) all threads apply b_i = sum_{k<=i} T[i][k] * v_k  (independent FMA
//     chains), store.
#define NV 8
#define DLEN 1024
#define NPROB 4096
#define NSTRIDE_F4 (NPROB * DLEN / 4)   // 1048576 float4 between n-slices
#define NG 36                           // lower-triangular entries

__device__ __forceinline__ float dot4(float4 a, float4 b) {
    return a.x * b.x + a.y * b.y + a.z * b.z + a.w * b.w;
}

__global__ void __launch_bounds__(256, 4)
gram_schmidt_kernel(const float* __restrict__ x, float* __restrict__ out) {
    const int p    = blockIdx.x;
    const int tid  = threadIdx.x;
    const int lane = tid & 31;
    const int warp = tid >> 5;

    const float4* __restrict__ xin =
        reinterpret_cast<const float4*>(x) + (size_t)p * (DLEN / 4) + tid;
    float4* __restrict__ xout =
        reinterpret_cast<float4*>(out) + (size_t)p * (DLEN / 4) + tid;

    __shared__ float part[NG][256];  // 36 KB: per-thread Gram partials
    __shared__ float Gf[NG];         // reduced Gram (packed lower tri)
    __shared__ float Tm[NG];         // GS transform matrix (packed lower tri)

    // ---- A: load all 8 vectors (batched LDG.128) + partial Gram ----
    float4 v[NV];
    #pragma unroll
    for (int n = 0; n < NV; n++) v[n] = xin[(size_t)n * NSTRIDE_F4];

    #pragma unroll
    for (int i = 0; i < NV; i++) {
        #pragma unroll
        for (int j = 0; j <= i; j++) {
            part[i * (i + 1) / 2 + j][tid] = dot4(v[i], v[j]);
        }
    }
    __syncthreads();

    // ---- B: cooperative reduction, warp w handles entries w, w+8, ... ----
    for (int t = warp; t < NG; t += 8) {
        const float4* row = reinterpret_cast<const float4*>(part[t]);
        float4 a = row[lane];
        float4 b = row[lane + 32];
        float s = (a.x + a.y) + (a.z + a.w) + (b.x + b.y) + (b.z + b.w);
        s += __shfl_xor_sync(0xffffffffu, s, 16);
        s += __shfl_xor_sync(0xffffffffu, s, 8);
        s += __shfl_xor_sync(0xffffffffu, s, 4);
        s += __shfl_xor_sync(0xffffffffu, s, 2);
        s += __shfl_xor_sync(0xffffffffu, s, 1);
        if (lane == 0) Gf[t] = s;
    }
    __syncthreads();

    // ---- C: warp 0 computes the triangular recursion (replicated lanes) ----
    if (warp == 0) {
        float G[NG];
        #pragma unroll
        for (int t = 0; t < NG; t++) G[t] = Gf[t];  // broadcast LDS

        float T[NG];
        {
            float inv = (G[0] > 0.0f) ? rsqrtf(G[0]) : 0.0f;
            T[0] = inv;
        }
        #pragma unroll
        for (int i = 1; i < NV; i++) {
            float c[NV];
            #pragma unroll
            for (int j = 0; j < i; j++) {
                float s = 0.0f;
                #pragma unroll
                for (int k = 0; k <= j; k++)
                    s += T[j * (j + 1) / 2 + k] * G[i * (i + 1) / 2 + k];
                c[j] = s;
            }
            float n2 = G[i * (i + 1) / 2 + i];
            #pragma unroll
            for (int j = 0; j < i; j++) n2 -= c[j] * c[j];
            float inv = (n2 > 0.0f) ? rsqrtf(n2) : 0.0f;

            #pragma unroll
            for (int k = 0; k < i; k++) {
                float s = 0.0f;
                #pragma unroll
                for (int j = k; j < i; j++)
                    s -= c[j] * T[j * (j + 1) / 2 + k];
                T[i * (i + 1) / 2 + k] = s * inv;
            }
            T[i * (i + 1) / 2 + i] = inv;
        }
        if (lane == 0) {
            #pragma unroll
            for (int t = 0; t < NG; t++) Tm[t] = T[t];
        }
    }
    __syncthreads();

    // ---- D: apply b_i = sum_{k<=i} T[i][k] v_k, store ----
    #pragma unroll
    for (int i = 0; i < NV; i++) {
        float4 acc = make_float4(0.0f, 0.0f, 0.0f, 0.0f);
        #pragma unroll
        for (int k = 0; k <= i; k++) {
            float t = Tm[i * (i + 1) / 2 + k];  // LDS broadcast
            acc.x += t * v[k].x;
            acc.y += t * v[k].y;
            acc.z += t * v[k].z;
            acc.w += t * v[k].w;
        }
        xout[(size_t)i * NSTRIDE_F4] = acc;
    }
}

extern "C" void kernel_launch(void* const* d_in, const int* in_sizes, int n_in,
                              void* d_out, int out_size) {
    const float* x = (const float*)d_in[0];
    float* out = (float*)d_out;
    gram_schmidt_kernel<<<NPROB, 256>>>(x, out);
}